// round 4
// baseline (speedup 1.0000x reference)
#include <cuda_runtime.h>
#include <cuda_fp16.h>
#include <cstdint>

// Fixed shapes
#define BB    2
#define NPTS  20000
#define MM    4096
#define SS    2
#define KK    25
#define JJ    64
#define PTS   16     // points per compute block
#define NTHR  256
#define GTHR  256    // gather threads (8 warps)
#define IPB   2048   // items per gather block
#define RNDS  (IPB / GTHR)          // 8 rounds
#define NITEMS (BB * MM * 50)       // 409600 items per channel-half
#define GBLKS  ((NITEMS / IPB) * 2) // 400 blocks (ch fastest)

// Dynamic smem layout for gather kernel (bytes)
#define SM_TAB   0                          // uint2[20000]          160000
#define SM_W     160000                     // float [8][1056]        33792
#define SM_IDX   193792                     // ushort[8][1056]        16896
#define SM_BASE  210688                     // int   [2048]            8192
#define SM_TOTAL 218880

// Static device scratch
__device__ __align__(16) __half g_xfh[BB * 2 * NPTS * 4]; // [b][chhalf][n][4ch] fp16
__device__ __align__(16) float  g_nf[BB * MM * 50 * 8];   // weighted-gather result
__device__ __align__(16) float  g_cwP[KK * 2 * 64 * 4];   // conv w packed
__device__ __align__(16) float  g_w0P[32 * 128 * 4];      // mlp0 w packed
__device__ __align__(16) float  g_w1P[32 * 256 * 4];      // mlp1 w packed
__device__ float g_wsum[64 * 2];                          // sum_k conv_w[o][c][k]

// ---------------------------------------------------------------------------
// Prep: fp16 gather table (channel-split), packed weights, center-fold sums,
// new_xyz passthrough.
// ---------------------------------------------------------------------------
__global__ void prep_kernel(const float* __restrict__ xyz,
                            const float* __restrict__ feat,
                            const float* __restrict__ new_xyz,
                            const float* __restrict__ conv_w,
                            const float* __restrict__ w0,
                            const float* __restrict__ w1,
                            float* __restrict__ out) {
    int i = blockIdx.x * blockDim.x + threadIdx.x;

    if (i < BB * NPTS) {
        const int b = i / NPTS;
        const int n = i - b * NPTS;
        float c[8];
        c[0] = xyz[i * 3 + 0];
        c[1] = xyz[i * 3 + 1];
#pragma unroll
        for (int q = 0; q < 6; q++) c[2 + q] = feat[i * 6 + q];

        __half2* lo = reinterpret_cast<__half2*>(g_xfh + ((size_t)(b * 2 + 0) * NPTS + n) * 4);
        __half2* hi = reinterpret_cast<__half2*>(g_xfh + ((size_t)(b * 2 + 1) * NPTS + n) * 4);
        lo[0] = __floats2half2_rn(c[0], c[1]);
        lo[1] = __floats2half2_rn(c[2], c[3]);
        hi[0] = __floats2half2_rn(c[4], c[5]);
        hi[1] = __floats2half2_rn(c[6], c[7]);
    }
    if (i < KK * 2 * 64 * 4) {          // ((k*2+c4)*64+o)*4+cc
        int cc = i & 3;
        int o  = (i >> 2) & 63;
        int t  = i >> 8;
        int c4 = t & 1;
        int k  = t >> 1;
        g_cwP[i] = conv_w[o * 200 + (c4 * 4 + cc) * 25 + k];
    }
    if (i < 32 * 128 * 4) {             // (c4*128+o)*4+cc
        int cc = i & 3;
        int o  = (i >> 2) & 127;
        int c4 = i >> 9;
        g_w0P[i] = w0[o * 128 + c4 * 4 + cc];
    }
    if (i < 32 * 256 * 4) {             // (c4*256+o)*4+cc
        int cc = i & 3;
        int o  = (i >> 2) & 255;
        int c4 = i >> 10;
        g_w1P[i] = w1[o * 128 + c4 * 4 + cc];
    }
    if (i < 128) {
        int o = i >> 1, c = i & 1;
        float s = 0.f;
#pragma unroll
        for (int k = 0; k < KK; k++) s += conv_w[o * 200 + c * 25 + k];
        g_wsum[i] = s;
    }
    if (i < BB * MM * 3) {
        out[i] = new_xyz[i];
    }
}

// ---------------------------------------------------------------------------
// Gather kernel v2: lane-owns-item, serial-j, shuffle-free.
// Block = 256 thr, 2048 contiguous items, one fp16 channel-half table in smem.
// ---------------------------------------------------------------------------
__global__ __launch_bounds__(GTHR) void gather_kernel(
    const int*   __restrict__ idx,
    const float* __restrict__ weight) {

    extern __shared__ __align__(16) char smem[];
    uint2*          s_tab  = reinterpret_cast<uint2*>(smem + SM_TAB);
    float*          s_w    = reinterpret_cast<float*>(smem + SM_W);
    unsigned short* s_idx  = reinterpret_cast<unsigned short*>(smem + SM_IDX);
    int*            s_base = reinterpret_cast<int*>(smem + SM_BASE);

    const int tid  = threadIdx.x;
    const int warp = tid >> 5;
    const int lane = tid & 31;
    const int blk  = blockIdx.x;
    const int ch   = blk & 1;
    const int ib   = blk >> 1;

    // Load table half (160 KB), coalesced. Table is per-batch: but items in this
    // block may span both batches? No: items are pid-major, pid = b*MM + m, so a
    // 2048-item run (≈41 points) stays within one batch except possibly at the
    // b boundary: item 204800*... pid boundary at pid=4096 -> item 204800, and
    // 204800 % 2048 == 0, so blocks never straddle batches. b from first item:
    const int b0 = (ib * IPB) / (MM * 50);
    {
        const uint2* gt = reinterpret_cast<const uint2*>(g_xfh) + (size_t)(b0 * 2 + ch) * NPTS;
#pragma unroll 8
        for (int i = tid; i < NPTS; i += GTHR) s_tab[i] = gt[i];
    }

    // Precompute per-item global base offsets (2048 of them)
    for (int t = tid; t < IPB; t += GTHR) {
        const int git = ib * IPB + t;
        const int pid = git / 50;
        const int sk  = git - pid * 50;
        const int s   = (sk >= 25) ? 1 : 0;
        const int k   = sk - s * 25;
        const int b   = pid >> 12;
        const int m   = pid & (MM - 1);
        s_base[t] = (((s * BB + b) * MM + m) * KK + k) * JJ;
    }
    __syncthreads();

    float* sw = s_w + warp * 1056;
    unsigned short* si = s_idx + warp * 1056;

    for (int rnd = 0; rnd < RNDS; rnd++) {
        const int tl0 = rnd * GTHR + warp * 32;   // warp's first local item

        float4 acc = make_float4(0.f, 0.f, 0.f, 0.f);

#pragma unroll
        for (int jc = 0; jc < 2; jc++) {
            // ---- stage: 32 items x 32 j, coalesced ----
#pragma unroll 4
            for (int i = 0; i < 32; i++) {
                const int gb = s_base[tl0 + i] + jc * 32 + lane;
                const int   iv = idx[gb];
                const float wv = weight[gb];
                si[i * 33 + lane] = (unsigned short)iv;
                sw[i * 33 + lane] = wv;
            }
            __syncwarp();

            // ---- consume: lane owns item (tl0+lane), serial j ----
            const int rowbase = lane * 33;
#pragma unroll 8
            for (int j = 0; j < 32; j++) {
                const int   r  = si[rowbase + j];
                const float wv = sw[rowbase + j];
                const uint2 row = s_tab[r];
                const __half2 h0 = *reinterpret_cast<const __half2*>(&row.x);
                const __half2 h1 = *reinterpret_cast<const __half2*>(&row.y);
                const float2 f0 = __half22float2(h0);
                const float2 f1 = __half22float2(h1);
                acc.x = fmaf(wv, f0.x, acc.x);
                acc.y = fmaf(wv, f0.y, acc.y);
                acc.z = fmaf(wv, f1.x, acc.z);
                acc.w = fmaf(wv, f1.y, acc.w);
            }
            __syncwarp();
        }

        // ---- store: lane's item result (4 channels of this half) ----
        const int git = ib * IPB + tl0 + lane;
        *reinterpret_cast<float4*>(g_nf + (size_t)git * 8 + ch * 4) = acc;
    }
}

// ---------------------------------------------------------------------------
// Compute kernel: conv + mlp0 + mlp1 (unchanged from R3).
// ---------------------------------------------------------------------------
__global__ __launch_bounds__(NTHR) void compute_kernel(
    const float* __restrict__ new_xyz,
    const float* __restrict__ conv_b,
    const float* __restrict__ mlp_b0,
    const float* __restrict__ mlp_b1,
    float* __restrict__ out) {

    __shared__ __align__(16) float s_buf[PTS * 50 * 8];
    __shared__ __align__(16) float s_x[PTS * 128];
    __shared__ float s_c[PTS * 2];

    const int tid  = threadIdx.x;
    const int warp = tid >> 5;
    const int lane = tid & 31;
    const int blk  = blockIdx.x;

    if (tid < PTS * 2) {
        int p = tid >> 1, c = tid & 1;
        s_c[tid] = new_xyz[(size_t)(blk * PTS + p) * 3 + c];
    }

    {
        float4* sb4 = reinterpret_cast<float4*>(s_buf);
        const float4* g4 = reinterpret_cast<const float4*>(g_nf) + (size_t)blk * (PTS * 100);
        for (int i = tid; i < PTS * 100; i += NTHR) sb4[i] = g4[i];
    }
    __syncthreads();

    // Phase B: conv 200->64 per scale
    {
        const int o  = lane + (warp & 1) * 32;
        const int pq = warp >> 1;
        const float4* cw4 = (const float4*)g_cwP;
        const float4* nf4 = (const float4*)s_buf;

        const float ws0 = g_wsum[o * 2 + 0];
        const float ws1 = g_wsum[o * 2 + 1];
        const float cb  = conv_b[o];

        float acc[SS][4];
#pragma unroll
        for (int pp = 0; pp < 4; pp++) {
            const float cx = s_c[(pq * 4 + pp) * 2 + 0];
            const float cy = s_c[(pq * 4 + pp) * 2 + 1];
            const float init = cb - ws0 * cx - ws1 * cy;
            acc[0][pp] = init;
            acc[1][pp] = init;
        }

        for (int k = 0; k < KK; k++) {
            const float4 wlo = cw4[(k * 2 + 0) * 64 + o];
            const float4 whi = cw4[(k * 2 + 1) * 64 + o];
#pragma unroll
            for (int s = 0; s < SS; s++) {
#pragma unroll
                for (int pp = 0; pp < 4; pp++) {
                    const int p = pq * 4 + pp;
                    const float4 alo = nf4[(p * 50 + s * 25 + k) * 2 + 0];
                    const float4 ahi = nf4[(p * 50 + s * 25 + k) * 2 + 1];
                    float a = acc[s][pp];
                    a = fmaf(wlo.x, alo.x, a);
                    a = fmaf(wlo.y, alo.y, a);
                    a = fmaf(wlo.z, alo.z, a);
                    a = fmaf(wlo.w, alo.w, a);
                    a = fmaf(whi.x, ahi.x, a);
                    a = fmaf(whi.y, ahi.y, a);
                    a = fmaf(whi.z, ahi.z, a);
                    a = fmaf(whi.w, ahi.w, a);
                    acc[s][pp] = a;
                }
            }
        }
#pragma unroll
        for (int s = 0; s < SS; s++)
#pragma unroll
            for (int pp = 0; pp < 4; pp++)
                s_x[(pq * 4 + pp) * 128 + s * 64 + o] = fmaxf(acc[s][pp], 0.f);
    }
    __syncthreads();

    // Phase C: mlp0 128->128
    {
        const int o  = lane + (warp & 3) * 32;
        const int p0 = (warp >> 2) * 8;
        const float4* w4 = (const float4*)g_w0P;
        const float4* x4 = (const float4*)s_x;

        float acc[8];
        const float b = mlp_b0[o];
#pragma unroll
        for (int pp = 0; pp < 8; pp++) acc[pp] = b;

        for (int c4 = 0; c4 < 32; c4++) {
            const float4 wvv = w4[c4 * 128 + o];
#pragma unroll
            for (int pp = 0; pp < 8; pp++) {
                const float4 a = x4[(p0 + pp) * 32 + c4];
                float t = acc[pp];
                t = fmaf(wvv.x, a.x, t);
                t = fmaf(wvv.y, a.y, t);
                t = fmaf(wvv.z, a.z, t);
                t = fmaf(wvv.w, a.w, t);
                acc[pp] = t;
            }
        }
        __syncthreads();
#pragma unroll
        for (int pp = 0; pp < 8; pp++)
            s_buf[(p0 + pp) * 128 + o] = fmaxf(acc[pp], 0.f);
    }
    __syncthreads();

    // Phase D: mlp1 128->256 + store
    {
        const int o  = lane + (warp & 3) * 32;
        const int p0 = (warp >> 2) * 8;
        const float4* w4 = (const float4*)g_w1P;
        const float4* h4 = (const float4*)s_buf;

        float acc0[8], acc1[8];
        const float ba = mlp_b1[o];
        const float bb = mlp_b1[o + 128];
#pragma unroll
        for (int pp = 0; pp < 8; pp++) { acc0[pp] = ba; acc1[pp] = bb; }

        for (int c4 = 0; c4 < 32; c4++) {
            const float4 wa = w4[c4 * 256 + o];
            const float4 wb = w4[c4 * 256 + o + 128];
#pragma unroll
            for (int pp = 0; pp < 8; pp++) {
                const float4 a = h4[(p0 + pp) * 32 + c4];
                float t0 = acc0[pp];
                float t1 = acc1[pp];
                t0 = fmaf(wa.x, a.x, t0);
                t1 = fmaf(wb.x, a.x, t1);
                t0 = fmaf(wa.y, a.y, t0);
                t1 = fmaf(wb.y, a.y, t1);
                t0 = fmaf(wa.z, a.z, t0);
                t1 = fmaf(wb.z, a.z, t1);
                t0 = fmaf(wa.w, a.w, t0);
                t1 = fmaf(wb.w, a.w, t1);
                acc0[pp] = t0;
                acc1[pp] = t1;
            }
        }
        const size_t ob = (size_t)BB * MM * 3;
#pragma unroll
        for (int pp = 0; pp < 8; pp++) {
            const int pid = blk * PTS + p0 + pp;
            out[ob + (size_t)pid * 256 + o]       = fmaxf(acc0[pp], 0.f);
            out[ob + (size_t)pid * 256 + o + 128] = fmaxf(acc1[pp], 0.f);
        }
    }
}

// ---------------------------------------------------------------------------
extern "C" void kernel_launch(void* const* d_in, const int* in_sizes, int n_in,
                              void* d_out, int out_size) {
    const float* xyz     = (const float*)d_in[0];
    const float* feature = (const float*)d_in[1];
    const float* new_xyz = (const float*)d_in[2];
    const int*   idx     = (const int*)  d_in[3];
    const float* weight  = (const float*)d_in[4];
    const float* conv_w  = (const float*)d_in[5];
    const float* conv_b  = (const float*)d_in[6];
    const float* mlp_w0  = (const float*)d_in[7];
    const float* mlp_b0  = (const float*)d_in[8];
    const float* mlp_w1  = (const float*)d_in[9];
    const float* mlp_b1  = (const float*)d_in[10];
    float* out = (float*)d_out;

    (void)in_sizes; (void)n_in; (void)out_size;

    cudaFuncSetAttribute(gather_kernel,
                         cudaFuncAttributeMaxDynamicSharedMemorySize,
                         SM_TOTAL);

    prep_kernel<<<(BB * NPTS + NTHR - 1) / NTHR, NTHR>>>(
        xyz, feature, new_xyz, conv_w, mlp_w0, mlp_w1, out);

    gather_kernel<<<GBLKS, GTHR, SM_TOTAL>>>(idx, weight);

    compute_kernel<<<(BB * MM) / PTS, NTHR>>>(
        new_xyz, conv_b, mlp_b0, mlp_b1, out);
}

// round 5
// speedup vs baseline: 3.0230x; 3.0230x over previous
#include <cuda_runtime.h>
#include <cuda_fp16.h>
#include <cstdint>

// Fixed shapes
#define BB    2
#define NPTS  20000
#define MM    4096
#define SS    2
#define KK    25
#define JJ    64
#define PTS   16     // points per compute block
#define NTHR  256
#define GTHR  1024   // gather threads (32 warps)
#define IPB   2048   // items per gather block
#define NWARP 32
#define IPW   8      // items per warp per pass
#define PASSES (IPB / (NWARP * IPW))   // 8
#define NITEMS (BB * MM * 50)          // 409600 items per channel-half
#define GBLKS  ((NITEMS / IPB) * 2)    // 400 blocks (ch fastest)

// Dynamic smem layout for gather kernel (bytes)
#define SM_TAB    0                    // uint2[20000]            160000
#define SM_STG    160000               // per-warp 1584B * 32      50688
#define WSTRIDE   1584                 // float w[8][33] + ushort idx[8][33]
#define SM_BASE   210688               // int[2048]                 8192
#define SM_TOTAL  218880

// Static device scratch
__device__ __align__(16) __half g_xfh[BB * 2 * NPTS * 4]; // [b][chhalf][n][4ch]
__device__ __align__(16) float  g_nf[BB * MM * 50 * 8];   // weighted-gather result
__device__ __align__(16) float  g_cwP[KK * 2 * 64 * 4];
__device__ __align__(16) float  g_w0P[32 * 128 * 4];
__device__ __align__(16) float  g_w1P[32 * 256 * 4];
__device__ float g_wsum[64 * 2];

// ---------------------------------------------------------------------------
// Prep
// ---------------------------------------------------------------------------
__global__ void prep_kernel(const float* __restrict__ xyz,
                            const float* __restrict__ feat,
                            const float* __restrict__ new_xyz,
                            const float* __restrict__ conv_w,
                            const float* __restrict__ w0,
                            const float* __restrict__ w1,
                            float* __restrict__ out) {
    int i = blockIdx.x * blockDim.x + threadIdx.x;

    if (i < BB * NPTS) {
        const int b = i / NPTS;
        const int n = i - b * NPTS;
        float c[8];
        c[0] = xyz[i * 3 + 0];
        c[1] = xyz[i * 3 + 1];
#pragma unroll
        for (int q = 0; q < 6; q++) c[2 + q] = feat[i * 6 + q];

        __half2* lo = reinterpret_cast<__half2*>(g_xfh + ((size_t)(b * 2 + 0) * NPTS + n) * 4);
        __half2* hi = reinterpret_cast<__half2*>(g_xfh + ((size_t)(b * 2 + 1) * NPTS + n) * 4);
        lo[0] = __floats2half2_rn(c[0], c[1]);
        lo[1] = __floats2half2_rn(c[2], c[3]);
        hi[0] = __floats2half2_rn(c[4], c[5]);
        hi[1] = __floats2half2_rn(c[6], c[7]);
    }
    if (i < KK * 2 * 64 * 4) {
        int cc = i & 3;
        int o  = (i >> 2) & 63;
        int t  = i >> 8;
        int c4 = t & 1;
        int k  = t >> 1;
        g_cwP[i] = conv_w[o * 200 + (c4 * 4 + cc) * 25 + k];
    }
    if (i < 32 * 128 * 4) {
        int cc = i & 3;
        int o  = (i >> 2) & 127;
        int c4 = i >> 9;
        g_w0P[i] = w0[o * 128 + c4 * 4 + cc];
    }
    if (i < 32 * 256 * 4) {
        int cc = i & 3;
        int o  = (i >> 2) & 255;
        int c4 = i >> 10;
        g_w1P[i] = w1[o * 128 + c4 * 4 + cc];
    }
    if (i < 128) {
        int o = i >> 1, c = i & 1;
        float s = 0.f;
#pragma unroll
        for (int k = 0; k < KK; k++) s += conv_w[o * 200 + c * 25 + k];
        g_wsum[i] = s;
    }
    if (i < BB * MM * 3) {
        out[i] = new_xyz[i];
    }
}

// ---------------------------------------------------------------------------
// Gather v3: 32 warps, 8 items/warp/pass, 4 lanes per item.
// Staging is fully coalesced (128B lines); consume is serial-j per lane with
// a 2-step shuffle reduction over 4 lanes.
// ---------------------------------------------------------------------------
__global__ __launch_bounds__(GTHR) void gather_kernel(
    const int*   __restrict__ idx,
    const float* __restrict__ weight) {

    extern __shared__ __align__(16) char smem[];
    uint2* s_tab  = reinterpret_cast<uint2*>(smem + SM_TAB);
    int*   s_base = reinterpret_cast<int*>(smem + SM_BASE);

    const int tid  = threadIdx.x;
    const int warp = tid >> 5;
    const int lane = tid & 31;
    const int blk  = blockIdx.x;
    const int ch   = blk & 1;
    const int ib   = blk >> 1;

    float*          sw = reinterpret_cast<float*>(smem + SM_STG + warp * WSTRIDE);
    unsigned short* si = reinterpret_cast<unsigned short*>(smem + SM_STG + warp * WSTRIDE + 8 * 33 * 4);

    // Block never straddles batches: 204800 % 2048 == 0.
    const int b0 = (ib * IPB) / (MM * 50);

    // Load fp16 table half (160 KB, coalesced, L2-resident source)
    {
        const uint2* gt = reinterpret_cast<const uint2*>(g_xfh) + (size_t)(b0 * 2 + ch) * NPTS;
        for (int i = tid; i < NPTS; i += GTHR) s_tab[i] = gt[i];
    }

    // Per-item global base offsets
    for (int t = tid; t < IPB; t += GTHR) {
        const int git = ib * IPB + t;
        const int pid = git / 50;
        const int sk  = git - pid * 50;
        const int s   = (sk >= 25) ? 1 : 0;
        const int k   = sk - s * 25;
        const int b   = pid >> 12;
        const int m   = pid & (MM - 1);
        s_base[t] = (((s * BB + b) * MM + m) * KK + k) * JJ;
    }
    __syncthreads();

    const int it    = lane >> 2;   // item within warp tile (0..7)
    const int jlane = lane & 3;    // j sub-lane

    for (int p = 0; p < PASSES; p++) {
        const int t0 = p * (NWARP * IPW) + warp * IPW;   // warp's first local item

        float4 acc = make_float4(0.f, 0.f, 0.f, 0.f);

#pragma unroll
        for (int jc = 0; jc < 2; jc++) {
            // ---- stage: 8 items x 32 j, one 128B line per LDG ----
#pragma unroll
            for (int t = 0; t < IPW; t++) {
                const int gb = s_base[t0 + t] + jc * 32 + lane;
                si[t * 33 + lane] = (unsigned short)idx[gb];
                sw[t * 33 + lane] = weight[gb];
            }
            __syncwarp();

            // ---- consume: lane handles js {jlane + 4t}, t = 0..7 ----
#pragma unroll
            for (int t = 0; t < 8; t++) {
                const int j  = jlane + 4 * t;
                const int   r  = si[it * 33 + j];
                const float wv = sw[it * 33 + j];
                const uint2 row = s_tab[r];
                const __half2 h0 = *reinterpret_cast<const __half2*>(&row.x);
                const __half2 h1 = *reinterpret_cast<const __half2*>(&row.y);
                const float2 f0 = __half22float2(h0);
                const float2 f1 = __half22float2(h1);
                acc.x = fmaf(wv, f0.x, acc.x);
                acc.y = fmaf(wv, f0.y, acc.y);
                acc.z = fmaf(wv, f1.x, acc.z);
                acc.w = fmaf(wv, f1.y, acc.w);
            }
            __syncwarp();
        }

        // ---- reduce over the 4 j-sub-lanes (xor 1, 2) ----
#pragma unroll
        for (int msk = 1; msk <= 2; msk <<= 1) {
            acc.x += __shfl_xor_sync(0xffffffffu, acc.x, msk);
            acc.y += __shfl_xor_sync(0xffffffffu, acc.y, msk);
            acc.z += __shfl_xor_sync(0xffffffffu, acc.z, msk);
            acc.w += __shfl_xor_sync(0xffffffffu, acc.w, msk);
        }
        if (jlane == 0) {
            const int git = ib * IPB + t0 + it;
            *reinterpret_cast<float4*>(g_nf + (size_t)git * 8 + ch * 4) = acc;
        }
    }
}

// ---------------------------------------------------------------------------
// Compute kernel: conv + mlp0 + mlp1 (unchanged, proven).
// ---------------------------------------------------------------------------
__global__ __launch_bounds__(NTHR) void compute_kernel(
    const float* __restrict__ new_xyz,
    const float* __restrict__ conv_b,
    const float* __restrict__ mlp_b0,
    const float* __restrict__ mlp_b1,
    float* __restrict__ out) {

    __shared__ __align__(16) float s_buf[PTS * 50 * 8];
    __shared__ __align__(16) float s_x[PTS * 128];
    __shared__ float s_c[PTS * 2];

    const int tid  = threadIdx.x;
    const int warp = tid >> 5;
    const int lane = tid & 31;
    const int blk  = blockIdx.x;

    if (tid < PTS * 2) {
        int p = tid >> 1, c = tid & 1;
        s_c[tid] = new_xyz[(size_t)(blk * PTS + p) * 3 + c];
    }

    {
        float4* sb4 = reinterpret_cast<float4*>(s_buf);
        const float4* g4 = reinterpret_cast<const float4*>(g_nf) + (size_t)blk * (PTS * 100);
        for (int i = tid; i < PTS * 100; i += NTHR) sb4[i] = g4[i];
    }
    __syncthreads();

    // Phase B: conv 200->64 per scale
    {
        const int o  = lane + (warp & 1) * 32;
        const int pq = warp >> 1;
        const float4* cw4 = (const float4*)g_cwP;
        const float4* nf4 = (const float4*)s_buf;

        const float ws0 = g_wsum[o * 2 + 0];
        const float ws1 = g_wsum[o * 2 + 1];
        const float cb  = conv_b[o];

        float acc[SS][4];
#pragma unroll
        for (int pp = 0; pp < 4; pp++) {
            const float cx = s_c[(pq * 4 + pp) * 2 + 0];
            const float cy = s_c[(pq * 4 + pp) * 2 + 1];
            const float init = cb - ws0 * cx - ws1 * cy;
            acc[0][pp] = init;
            acc[1][pp] = init;
        }

        for (int k = 0; k < KK; k++) {
            const float4 wlo = cw4[(k * 2 + 0) * 64 + o];
            const float4 whi = cw4[(k * 2 + 1) * 64 + o];
#pragma unroll
            for (int s = 0; s < SS; s++) {
#pragma unroll
                for (int pp = 0; pp < 4; pp++) {
                    const int p = pq * 4 + pp;
                    const float4 alo = nf4[(p * 50 + s * 25 + k) * 2 + 0];
                    const float4 ahi = nf4[(p * 50 + s * 25 + k) * 2 + 1];
                    float a = acc[s][pp];
                    a = fmaf(wlo.x, alo.x, a);
                    a = fmaf(wlo.y, alo.y, a);
                    a = fmaf(wlo.z, alo.z, a);
                    a = fmaf(wlo.w, alo.w, a);
                    a = fmaf(whi.x, ahi.x, a);
                    a = fmaf(whi.y, ahi.y, a);
                    a = fmaf(whi.z, ahi.z, a);
                    a = fmaf(whi.w, ahi.w, a);
                    acc[s][pp] = a;
                }
            }
        }
#pragma unroll
        for (int s = 0; s < SS; s++)
#pragma unroll
            for (int pp = 0; pp < 4; pp++)
                s_x[(pq * 4 + pp) * 128 + s * 64 + o] = fmaxf(acc[s][pp], 0.f);
    }
    __syncthreads();

    // Phase C: mlp0 128->128
    {
        const int o  = lane + (warp & 3) * 32;
        const int p0 = (warp >> 2) * 8;
        const float4* w4 = (const float4*)g_w0P;
        const float4* x4 = (const float4*)s_x;

        float acc[8];
        const float b = mlp_b0[o];
#pragma unroll
        for (int pp = 0; pp < 8; pp++) acc[pp] = b;

        for (int c4 = 0; c4 < 32; c4++) {
            const float4 wvv = w4[c4 * 128 + o];
#pragma unroll
            for (int pp = 0; pp < 8; pp++) {
                const float4 a = x4[(p0 + pp) * 32 + c4];
                float t = acc[pp];
                t = fmaf(wvv.x, a.x, t);
                t = fmaf(wvv.y, a.y, t);
                t = fmaf(wvv.z, a.z, t);
                t = fmaf(wvv.w, a.w, t);
                acc[pp] = t;
            }
        }
        __syncthreads();
#pragma unroll
        for (int pp = 0; pp < 8; pp++)
            s_buf[(p0 + pp) * 128 + o] = fmaxf(acc[pp], 0.f);
    }
    __syncthreads();

    // Phase D: mlp1 128->256 + store
    {
        const int o  = lane + (warp & 3) * 32;
        const int p0 = (warp >> 2) * 8;
        const float4* w4 = (const float4*)g_w1P;
        const float4* h4 = (const float4*)s_buf;

        float acc0[8], acc1[8];
        const float ba = mlp_b1[o];
        const float bb = mlp_b1[o + 128];
#pragma unroll
        for (int pp = 0; pp < 8; pp++) { acc0[pp] = ba; acc1[pp] = bb; }

        for (int c4 = 0; c4 < 32; c4++) {
            const float4 wa = w4[c4 * 256 + o];
            const float4 wb = w4[c4 * 256 + o + 128];
#pragma unroll
            for (int pp = 0; pp < 8; pp++) {
                const float4 a = h4[(p0 + pp) * 32 + c4];
                float t0 = acc0[pp];
                float t1 = acc1[pp];
                t0 = fmaf(wa.x, a.x, t0);
                t1 = fmaf(wb.x, a.x, t1);
                t0 = fmaf(wa.y, a.y, t0);
                t1 = fmaf(wb.y, a.y, t1);
                t0 = fmaf(wa.z, a.z, t0);
                t1 = fmaf(wb.z, a.z, t1);
                t0 = fmaf(wa.w, a.w, t0);
                t1 = fmaf(wb.w, a.w, t1);
                acc0[pp] = t0;
                acc1[pp] = t1;
            }
        }
        const size_t ob = (size_t)BB * MM * 3;
#pragma unroll
        for (int pp = 0; pp < 8; pp++) {
            const int pid = blk * PTS + p0 + pp;
            out[ob + (size_t)pid * 256 + o]       = fmaxf(acc0[pp], 0.f);
            out[ob + (size_t)pid * 256 + o + 128] = fmaxf(acc1[pp], 0.f);
        }
    }
}

// ---------------------------------------------------------------------------
extern "C" void kernel_launch(void* const* d_in, const int* in_sizes, int n_in,
                              void* d_out, int out_size) {
    const float* xyz     = (const float*)d_in[0];
    const float* feature = (const float*)d_in[1];
    const float* new_xyz = (const float*)d_in[2];
    const int*   idx     = (const int*)  d_in[3];
    const float* weight  = (const float*)d_in[4];
    const float* conv_w  = (const float*)d_in[5];
    const float* conv_b  = (const float*)d_in[6];
    const float* mlp_w0  = (const float*)d_in[7];
    const float* mlp_b0  = (const float*)d_in[8];
    const float* mlp_w1  = (const float*)d_in[9];
    const float* mlp_b1  = (const float*)d_in[10];
    float* out = (float*)d_out;

    (void)in_sizes; (void)n_in; (void)out_size;

    cudaFuncSetAttribute(gather_kernel,
                         cudaFuncAttributeMaxDynamicSharedMemorySize,
                         SM_TOTAL);

    prep_kernel<<<(BB * NPTS + NTHR - 1) / NTHR, NTHR>>>(
        xyz, feature, new_xyz, conv_w, mlp_w0, mlp_w1, out);

    gather_kernel<<<GBLKS, GTHR, SM_TOTAL>>>(idx, weight);

    compute_kernel<<<(BB * MM) / PTS, NTHR>>>(
        new_xyz, conv_b, mlp_b0, mlp_b1, out);
}

// round 6
// speedup vs baseline: 5.0788x; 1.6801x over previous
#include <cuda_runtime.h>
#include <cuda_fp16.h>
#include <cstdint>

// Fixed shapes
#define BB    2
#define NPTS  20000
#define MM    4096
#define SS    2
#define KK    25
#define JJ    64
#define PTS   16     // points per compute block
#define NTHR  256
#define GTHR  1024   // gather threads (32 warps)
#define NWARP 32
#define IPW   8      // items per warp per pass
#define IPB   2048   // items per gather block (= 8 passes)
#define PASSES (IPB / (NWARP * IPW))     // 8
#define CHUNKS (PASSES * 2)              // 16 (2 j-chunks per pass)
#define NITEMS (BB * MM * 50)            // 409600 items
#define GBLKS  ((NITEMS / IPB) * 2)      // 400 blocks (ch fastest)

// Dynamic smem layout (bytes)
#define SM_TAB    0                      // uint2[20000]          160000
#define SM_STG    160000                 // uint2[8][34] per warp: 2176 * 32 = 69632
#define WSTRIDE   2176
#define SM_TOTAL  229632                 // <= 232448

// Static device scratch
__device__ __align__(16) __half g_xfh[BB * 2 * NPTS * 4]; // [b][chhalf][n][4ch]
__device__ __align__(16) float  g_nf[BB * MM * 50 * 8];
__device__ __align__(16) float  g_cwP[KK * 2 * 64 * 4];
__device__ __align__(16) float  g_w0P[32 * 128 * 4];
__device__ __align__(16) float  g_w1P[32 * 256 * 4];
__device__ float g_wsum[64 * 2];

// ---------------------------------------------------------------------------
// Prep
// ---------------------------------------------------------------------------
__global__ void prep_kernel(const float* __restrict__ xyz,
                            const float* __restrict__ feat,
                            const float* __restrict__ new_xyz,
                            const float* __restrict__ conv_w,
                            const float* __restrict__ w0,
                            const float* __restrict__ w1,
                            float* __restrict__ out) {
    int i = blockIdx.x * blockDim.x + threadIdx.x;

    if (i < BB * NPTS) {
        const int b = i / NPTS;
        const int n = i - b * NPTS;
        float c[8];
        c[0] = xyz[i * 3 + 0];
        c[1] = xyz[i * 3 + 1];
#pragma unroll
        for (int q = 0; q < 6; q++) c[2 + q] = feat[i * 6 + q];

        __half2* lo = reinterpret_cast<__half2*>(g_xfh + ((size_t)(b * 2 + 0) * NPTS + n) * 4);
        __half2* hi = reinterpret_cast<__half2*>(g_xfh + ((size_t)(b * 2 + 1) * NPTS + n) * 4);
        lo[0] = __floats2half2_rn(c[0], c[1]);
        lo[1] = __floats2half2_rn(c[2], c[3]);
        hi[0] = __floats2half2_rn(c[4], c[5]);
        hi[1] = __floats2half2_rn(c[6], c[7]);
    }
    if (i < KK * 2 * 64 * 4) {
        int cc = i & 3;
        int o  = (i >> 2) & 63;
        int t  = i >> 8;
        int c4 = t & 1;
        int k  = t >> 1;
        g_cwP[i] = conv_w[o * 200 + (c4 * 4 + cc) * 25 + k];
    }
    if (i < 32 * 128 * 4) {
        int cc = i & 3;
        int o  = (i >> 2) & 127;
        int c4 = i >> 9;
        g_w0P[i] = w0[o * 128 + c4 * 4 + cc];
    }
    if (i < 32 * 256 * 4) {
        int cc = i & 3;
        int o  = (i >> 2) & 255;
        int c4 = i >> 10;
        g_w1P[i] = w1[o * 128 + c4 * 4 + cc];
    }
    if (i < 128) {
        int o = i >> 1, c = i & 1;
        float s = 0.f;
#pragma unroll
        for (int k = 0; k < KK; k++) s += conv_w[o * 200 + c * 25 + k];
        g_wsum[i] = s;
    }
    if (i < BB * MM * 3) {
        out[i] = new_xyz[i];
    }
}

// Per-item global base offset from linear item id (0..409599)
__device__ __forceinline__ int item_base(int git) {
    const int pid = git / 50;              // b*4096 + m
    const int sk  = git - pid * 50;
    const int s   = (sk >= 25) ? 1 : 0;
    const int k   = sk - s * 25;
    const int b   = pid >> 12;
    const int m   = pid & (MM - 1);
    return (((s * BB + b) * MM + m) * KK + k) * JJ;
}

// ---------------------------------------------------------------------------
// Gather v4: pipelined staging, packed uint2, 4 lanes per item.
// ---------------------------------------------------------------------------
__global__ __launch_bounds__(GTHR) void gather_kernel(
    const int*   __restrict__ idx,
    const float* __restrict__ weight) {

    extern __shared__ __align__(16) char smem[];
    uint2* s_tab = reinterpret_cast<uint2*>(smem + SM_TAB);

    const int tid  = threadIdx.x;
    const int warp = tid >> 5;
    const int lane = tid & 31;
    const int blk  = blockIdx.x;
    const int ch   = blk & 1;
    const int ib   = blk >> 1;

    uint2* stg = reinterpret_cast<uint2*>(smem + SM_STG + warp * WSTRIDE);

    // Block never straddles batches: 204800 % 2048 == 0.
    const int b0 = (ib * IPB) / (MM * 50);

    // Load fp16 table half (160 KB)
    {
        const uint2* gt = reinterpret_cast<const uint2*>(g_xfh) + (size_t)(b0 * 2 + ch) * NPTS;
        for (int i = tid; i < NPTS; i += GTHR) s_tab[i] = gt[i];
    }
    __syncthreads();

    const int it    = lane >> 2;   // item within warp tile (0..7)
    const int jlane = lane & 3;    // j quarter

    // ---- prefetch chunk 0 ----
    int   pi[IPW];
    float pw[IPW];
    {
        const int t0 = ib * IPB + warp * IPW;   // pass 0
#pragma unroll
        for (int t = 0; t < IPW; t++) {
            const int gb = item_base(t0 + t) + lane;   // jc = 0
            pi[t] = idx[gb];
            pw[t] = weight[gb];
        }
    }

    float4 acc = make_float4(0.f, 0.f, 0.f, 0.f);

    for (int c = 0; c < CHUNKS; c++) {
        const int p  = c >> 1;
        const int jc = c & 1;

        // ---- commit prefetched chunk to smem staging ----
#pragma unroll
        for (int t = 0; t < IPW; t++)
            stg[t * 34 + lane] = make_uint2((unsigned)pi[t], __float_as_uint(pw[t]));
        __syncwarp();

        // ---- prefetch next chunk (overlaps consume) ----
        if (c + 1 < CHUNKS) {
            const int pn  = (c + 1) >> 1;
            const int jcn = (c + 1) & 1;
            const int t0  = ib * IPB + pn * (NWARP * IPW) + warp * IPW;
#pragma unroll
            for (int t = 0; t < IPW; t++) {
                const int gb = item_base(t0 + t) + jcn * 32 + lane;
                pi[t] = idx[gb];
                pw[t] = weight[gb];
            }
        }

        // ---- consume: lane handles item `it`, j = jlane*8 + u (u=0..7) ----
        const uint2* myrow = stg + it * 34 + jlane * 8;
#pragma unroll
        for (int u2 = 0; u2 < 4; u2++) {
            // LDS.128: two packed (idx,w) pairs
            const uint4 pk = *reinterpret_cast<const uint4*>(myrow + u2 * 2);

            {
                const uint2 row = s_tab[pk.x];
                const float wv  = __uint_as_float(pk.y);
                const float2 f0 = __half22float2(*reinterpret_cast<const __half2*>(&row.x));
                const float2 f1 = __half22float2(*reinterpret_cast<const __half2*>(&row.y));
                acc.x = fmaf(wv, f0.x, acc.x);
                acc.y = fmaf(wv, f0.y, acc.y);
                acc.z = fmaf(wv, f1.x, acc.z);
                acc.w = fmaf(wv, f1.y, acc.w);
            }
            {
                const uint2 row = s_tab[pk.z];
                const float wv  = __uint_as_float(pk.w);
                const float2 f0 = __half22float2(*reinterpret_cast<const __half2*>(&row.x));
                const float2 f1 = __half22float2(*reinterpret_cast<const __half2*>(&row.y));
                acc.x = fmaf(wv, f0.x, acc.x);
                acc.y = fmaf(wv, f0.y, acc.y);
                acc.z = fmaf(wv, f1.x, acc.z);
                acc.w = fmaf(wv, f1.y, acc.w);
            }
        }
        __syncwarp();

        if (jc == 1) {
            // item complete: reduce over the 4 j-quarters
#pragma unroll
            for (int msk = 1; msk <= 2; msk <<= 1) {
                acc.x += __shfl_xor_sync(0xffffffffu, acc.x, msk);
                acc.y += __shfl_xor_sync(0xffffffffu, acc.y, msk);
                acc.z += __shfl_xor_sync(0xffffffffu, acc.z, msk);
                acc.w += __shfl_xor_sync(0xffffffffu, acc.w, msk);
            }
            if (jlane == 0) {
                const int git = ib * IPB + p * (NWARP * IPW) + warp * IPW + it;
                *reinterpret_cast<float4*>(g_nf + (size_t)git * 8 + ch * 4) = acc;
            }
            acc = make_float4(0.f, 0.f, 0.f, 0.f);
        }
    }
}

// ---------------------------------------------------------------------------
// Compute kernel (proven): conv + mlp0 + mlp1.
// ---------------------------------------------------------------------------
__global__ __launch_bounds__(NTHR) void compute_kernel(
    const float* __restrict__ new_xyz,
    const float* __restrict__ conv_b,
    const float* __restrict__ mlp_b0,
    const float* __restrict__ mlp_b1,
    float* __restrict__ out) {

    __shared__ __align__(16) float s_buf[PTS * 50 * 8];
    __shared__ __align__(16) float s_x[PTS * 128];
    __shared__ float s_c[PTS * 2];

    const int tid  = threadIdx.x;
    const int warp = tid >> 5;
    const int lane = tid & 31;
    const int blk  = blockIdx.x;

    if (tid < PTS * 2) {
        int p = tid >> 1, c = tid & 1;
        s_c[tid] = new_xyz[(size_t)(blk * PTS + p) * 3 + c];
    }

    {
        float4* sb4 = reinterpret_cast<float4*>(s_buf);
        const float4* g4 = reinterpret_cast<const float4*>(g_nf) + (size_t)blk * (PTS * 100);
        for (int i = tid; i < PTS * 100; i += NTHR) sb4[i] = g4[i];
    }
    __syncthreads();

    // Phase B: conv 200->64 per scale
    {
        const int o  = lane + (warp & 1) * 32;
        const int pq = warp >> 1;
        const float4* cw4 = (const float4*)g_cwP;
        const float4* nf4 = (const float4*)s_buf;

        const float ws0 = g_wsum[o * 2 + 0];
        const float ws1 = g_wsum[o * 2 + 1];
        const float cb  = conv_b[o];

        float acc[SS][4];
#pragma unroll
        for (int pp = 0; pp < 4; pp++) {
            const float cx = s_c[(pq * 4 + pp) * 2 + 0];
            const float cy = s_c[(pq * 4 + pp) * 2 + 1];
            const float init = cb - ws0 * cx - ws1 * cy;
            acc[0][pp] = init;
            acc[1][pp] = init;
        }

        for (int k = 0; k < KK; k++) {
            const float4 wlo = cw4[(k * 2 + 0) * 64 + o];
            const float4 whi = cw4[(k * 2 + 1) * 64 + o];
#pragma unroll
            for (int s = 0; s < SS; s++) {
#pragma unroll
                for (int pp = 0; pp < 4; pp++) {
                    const int p = pq * 4 + pp;
                    const float4 alo = nf4[(p * 50 + s * 25 + k) * 2 + 0];
                    const float4 ahi = nf4[(p * 50 + s * 25 + k) * 2 + 1];
                    float a = acc[s][pp];
                    a = fmaf(wlo.x, alo.x, a);
                    a = fmaf(wlo.y, alo.y, a);
                    a = fmaf(wlo.z, alo.z, a);
                    a = fmaf(wlo.w, alo.w, a);
                    a = fmaf(whi.x, ahi.x, a);
                    a = fmaf(whi.y, ahi.y, a);
                    a = fmaf(whi.z, ahi.z, a);
                    a = fmaf(whi.w, ahi.w, a);
                    acc[s][pp] = a;
                }
            }
        }
#pragma unroll
        for (int s = 0; s < SS; s++)
#pragma unroll
            for (int pp = 0; pp < 4; pp++)
                s_x[(pq * 4 + pp) * 128 + s * 64 + o] = fmaxf(acc[s][pp], 0.f);
    }
    __syncthreads();

    // Phase C: mlp0 128->128
    {
        const int o  = lane + (warp & 3) * 32;
        const int p0 = (warp >> 2) * 8;
        const float4* w4 = (const float4*)g_w0P;
        const float4* x4 = (const float4*)s_x;

        float acc[8];
        const float b = mlp_b0[o];
#pragma unroll
        for (int pp = 0; pp < 8; pp++) acc[pp] = b;

        for (int c4 = 0; c4 < 32; c4++) {
            const float4 wvv = w4[c4 * 128 + o];
#pragma unroll
            for (int pp = 0; pp < 8; pp++) {
                const float4 a = x4[(p0 + pp) * 32 + c4];
                float t = acc[pp];
                t = fmaf(wvv.x, a.x, t);
                t = fmaf(wvv.y, a.y, t);
                t = fmaf(wvv.z, a.z, t);
                t = fmaf(wvv.w, a.w, t);
                acc[pp] = t;
            }
        }
        __syncthreads();
#pragma unroll
        for (int pp = 0; pp < 8; pp++)
            s_buf[(p0 + pp) * 128 + o] = fmaxf(acc[pp], 0.f);
    }
    __syncthreads();

    // Phase D: mlp1 128->256 + store
    {
        const int o  = lane + (warp & 3) * 32;
        const int p0 = (warp >> 2) * 8;
        const float4* w4 = (const float4*)g_w1P;
        const float4* h4 = (const float4*)s_buf;

        float acc0[8], acc1[8];
        const float ba = mlp_b1[o];
        const float bb = mlp_b1[o + 128];
#pragma unroll
        for (int pp = 0; pp < 8; pp++) { acc0[pp] = ba; acc1[pp] = bb; }

        for (int c4 = 0; c4 < 32; c4++) {
            const float4 wa = w4[c4 * 256 + o];
            const float4 wb = w4[c4 * 256 + o + 128];
#pragma unroll
            for (int pp = 0; pp < 8; pp++) {
                const float4 a = h4[(p0 + pp) * 32 + c4];
                float t0 = acc0[pp];
                float t1 = acc1[pp];
                t0 = fmaf(wa.x, a.x, t0);
                t1 = fmaf(wb.x, a.x, t1);
                t0 = fmaf(wa.y, a.y, t0);
                t1 = fmaf(wb.y, a.y, t1);
                t0 = fmaf(wa.z, a.z, t0);
                t1 = fmaf(wb.z, a.z, t1);
                t0 = fmaf(wa.w, a.w, t0);
                t1 = fmaf(wb.w, a.w, t1);
                acc0[pp] = t0;
                acc1[pp] = t1;
            }
        }
        const size_t ob = (size_t)BB * MM * 3;
#pragma unroll
        for (int pp = 0; pp < 8; pp++) {
            const int pid = blk * PTS + p0 + pp;
            out[ob + (size_t)pid * 256 + o]       = fmaxf(acc0[pp], 0.f);
            out[ob + (size_t)pid * 256 + o + 128] = fmaxf(acc1[pp], 0.f);
        }
    }
}

// ---------------------------------------------------------------------------
extern "C" void kernel_launch(void* const* d_in, const int* in_sizes, int n_in,
                              void* d_out, int out_size) {
    const float* xyz     = (const float*)d_in[0];
    const float* feature = (const float*)d_in[1];
    const float* new_xyz = (const float*)d_in[2];
    const int*   idx     = (const int*)  d_in[3];
    const float* weight  = (const float*)d_in[4];
    const float* conv_w  = (const float*)d_in[5];
    const float* conv_b  = (const float*)d_in[6];
    const float* mlp_w0  = (const float*)d_in[7];
    const float* mlp_b0  = (const float*)d_in[8];
    const float* mlp_w1  = (const float*)d_in[9];
    const float* mlp_b1  = (const float*)d_in[10];
    float* out = (float*)d_out;

    (void)in_sizes; (void)n_in; (void)out_size;

    cudaFuncSetAttribute(gather_kernel,
                         cudaFuncAttributeMaxDynamicSharedMemorySize,
                         SM_TOTAL);

    prep_kernel<<<(BB * NPTS + NTHR - 1) / NTHR, NTHR>>>(
        xyz, feature, new_xyz, conv_w, mlp_w0, mlp_w1, out);

    gather_kernel<<<GBLKS, GTHR, SM_TOTAL>>>(idx, weight);

    compute_kernel<<<(BB * MM) / PTS, NTHR>>>(
        new_xyz, conv_b, mlp_b0, mlp_b1, out);
}